// round 13
// baseline (speedup 1.0000x reference)
#include <cuda_runtime.h>

// Scratch (device globals — no runtime allocation allowed)
__device__ float g_part   [4 * 128 * 1024]; // partial column sums of v (128 chunks of 8 rows)
__device__ float g_rowpart[8 * 4 * 1024];   // split-K partials of vsum @ Wv
__device__ float g_wosum  [64 * 1024];      // WoSum[d][m] = sum_j Wo[j*64+d][m]
__device__ float g_outrows[64 * 1024];      // 16 distinct out rows per batch
__device__ unsigned int g_fc, g_fw, g_f2;   // phase counters (reset by ln node)

static __device__ __forceinline__ void f4add(float4& a, const float4& b) {
    a.x += b.x; a.y += b.y; a.z += b.z; a.w += b.w;
}

static __device__ __forceinline__ void signal(unsigned int* f) {
    __threadfence();
    __syncthreads();
    if (threadIdx.x == 0) atomicAdd(f, 1u);
}

static __device__ __forceinline__ void spin_until(unsigned int* f, unsigned int tgt) {
    if (threadIdx.x == 0) {
        while (atomicAdd(f, 0u) < tgt) { }
    }
    __syncthreads();
    __threadfence();
}

// ---------------------------------------------------------------------------
// Node 1 (672 blocks, 20 KB smem -> 8 blocks/SM -> 1184 cap, all resident):
//   [0,512)   colsum of v (8-row chunks)          -> g_fc (512)
//   [512,576) wosum of Wo                         -> g_fw (64)
//   [576,608) vwv producers  (wait fc)            -> g_f2 (32)
//   [608,672) outrows        (wait fw, then f2)
// ---------------------------------------------------------------------------
__global__ __launch_bounds__(256) void pm_kernel(const float* __restrict__ v,
                                                 const float* __restrict__ Wo,
                                                 const float* __restrict__ Wv,
                                                 float* __restrict__ part,
                                                 float* __restrict__ wosum,
                                                 float* __restrict__ rowpart,
                                                 float* __restrict__ outrows) {
    __shared__ float smem_buf[64 * 64 + 16 * 64];   // 20 KB union
    const int bx = blockIdx.x;
    const int t  = threadIdx.x;

    if (bx < 512) {
        // ---- colsum of v: 8-row chunk ----
        const int s = bx >> 2, b = bx & 3;
        const float4* p = (const float4*)(v + ((size_t)(b * 1024 + s * 8)) * 1024) + t;
        float4 buf[8];
#pragma unroll
        for (int i = 0; i < 8; ++i) buf[i] = p[(size_t)i * 256];
        float4 acc = buf[0];
#pragma unroll
        for (int i = 1; i < 8; ++i) f4add(acc, buf[i]);
        ((float4*)(part + (size_t)(b * 128 + s) * 1024))[t] = acc;
        signal(&g_fc);
    } else if (bx < 576) {
        // ---- wosum ----
        const int d = bx - 512;      // 0..63
        const float4* src = (const float4*)(Wo + (size_t)d * 1024) + t;
        float4 a0 = make_float4(0.f, 0.f, 0.f, 0.f);
        float4 a1 = make_float4(0.f, 0.f, 0.f, 0.f);
        float4 a2 = make_float4(0.f, 0.f, 0.f, 0.f);
        float4 a3 = make_float4(0.f, 0.f, 0.f, 0.f);
#pragma unroll
        for (int j = 0; j < 16; j += 4) {
            float4 x0 = src[(size_t)(j + 0) * 64 * 256];
            float4 x1 = src[(size_t)(j + 1) * 64 * 256];
            float4 x2 = src[(size_t)(j + 2) * 64 * 256];
            float4 x3 = src[(size_t)(j + 3) * 64 * 256];
            f4add(a0, x0); f4add(a1, x1); f4add(a2, x2); f4add(a3, x3);
        }
        f4add(a0, a1); f4add(a2, a3); f4add(a0, a2);
        ((float4*)(wosum + (size_t)d * 1024))[t] = a0;
        signal(&g_fw);
    } else if (bx < 608) {
        // ---- vwv producer: fold 128 part-chunks, partial GEMM vs Wv ----
        float* vs = smem_buf;                        // [4][128]
        const int r = bx - 576, oc = r & 3, kc = r >> 2;
        spin_until(&g_fc, 512u);
        for (int idx = t; idx < 512; idx += 256) {
            int b = idx >> 7, kk = idx & 127;
            const float* pp = part + (size_t)(b * 128) * 1024 + kc * 128 + kk;
            float acc = 0.f;
            float buf[8];
#pragma unroll
            for (int g = 0; g < 16; ++g) {
#pragma unroll
                for (int i = 0; i < 8; ++i) buf[i] = pp[(size_t)(g * 8 + i) * 1024];
#pragma unroll
                for (int i = 0; i < 8; ++i) acc += buf[i];
            }
            vs[b * 128 + kk] = acc;
        }
        __syncthreads();
        const int o = oc * 256 + t;
        float a0 = 0.f, a1 = 0.f, a2 = 0.f, a3 = 0.f;
#pragma unroll 8
        for (int kk = 0; kk < 128; ++kk) {
            float w = Wv[(size_t)(kc * 128 + kk) * 1024 + o];
            a0 = fmaf(vs[0 * 128 + kk], w, a0);
            a1 = fmaf(vs[1 * 128 + kk], w, a1);
            a2 = fmaf(vs[2 * 128 + kk], w, a2);
            a3 = fmaf(vs[3 * 128 + kk], w, a3);
        }
        float* rp = rowpart + (size_t)kc * 4096;
        rp[0 * 1024 + o] = a0;
        rp[1 * 1024 + o] = a1;
        rp[2 * 1024 + o] = a2;
        rp[3 * 1024 + o] = a3;
        signal(&g_f2);
    } else {
        // ---- outrows consumer: ws (64 d x 64 m floats) + rs (16 bn x 64 d) ----
        float4* ws = (float4*)smem_buf;              // [64][16] float4 = 16 KB
        float*  rs = smem_buf + 64 * 64;             // [16][64] = 4 KB
        const int r = bx - 608, mc = r & 15, bng = r >> 4;

        spin_until(&g_fw, 64u);
#pragma unroll
        for (int it = 0; it < 4; ++it) {
            int idx = t + it * 256;            // 0..1023
            int d = idx >> 4, m4 = idx & 15;
            ws[d * 16 + m4] = ((const float4*)wosum)[(size_t)d * 256 + mc * 16 + m4];
        }

        spin_until(&g_f2, 32u);
#pragma unroll
        for (int it = 0; it < 4; ++it) {
            int idx = t + it * 256;            // 0..1023
            int bnl = idx >> 6, d = idx & 63;
            int bn = bng * 16 + bnl;
            int b = bn >> 4, o = (bn & 15) * 64 + d;
            float buf[8];
#pragma unroll
            for (int kc = 0; kc < 8; ++kc)
                buf[kc] = rowpart[(size_t)(kc * 4 + b) * 1024 + o];
            float a = 0.f;
#pragma unroll
            for (int kc = 0; kc < 8; ++kc) a += buf[kc];
            rs[bnl * 64 + d] = a;
        }
        __syncthreads();

        const int bnl = t >> 4, m4 = t & 15;
        float4 acc = make_float4(0.f, 0.f, 0.f, 0.f);
#pragma unroll
        for (int d = 0; d < 64; ++d) {
            float a = rs[bnl * 64 + d];
            float4 w = ws[d * 16 + m4];
            acc.x = fmaf(a, w.x, acc.x);
            acc.y = fmaf(a, w.y, acc.y);
            acc.z = fmaf(a, w.z, acc.z);
            acc.w = fmaf(a, w.w, acc.w);
        }
        const int bn = bng * 16 + bnl;
        ((float4*)outrows)[(size_t)bn * 256 + mc * 16 + m4] = acc;
    }
}

// ---------------------------------------------------------------------------
// Node 2: residual add + LayerNorm, FOUR WARPS PER ROW, streaming stores.
// Block 0 thread 0 resets the phase counters for the next graph replay.
// ---------------------------------------------------------------------------
__global__ __launch_bounds__(256) void ln_kernel(const float* __restrict__ outrows,
                                                 const float* __restrict__ q,
                                                 const float* __restrict__ gamma,
                                                 const float* __restrict__ beta,
                                                 float* __restrict__ out) {
    __shared__ float2 psum[8];
    if (blockIdx.x == 0 && threadIdx.x == 0) {
        g_fc = 0u; g_fw = 0u; g_f2 = 0u;   // safe: pm node fully done
    }
    const int warp = threadIdx.x >> 5, lane = threadIdx.x & 31;
    const int rloc = warp >> 2, qtr = warp & 3;
    const int row  = blockIdx.x * 2 + rloc;            // 0..4095
    const int bn   = (row >> 10) * 16 + ((row & 1023) >> 6);
    const int f4   = qtr * 64 + lane;                  // float4 index base

    const float4* yp = (const float4*)(outrows + (size_t)bn * 1024) + f4;
    const float4* rp = (const float4*)(q + (size_t)row * 1024) + f4;

    float4 y0 = yp[0], y1 = yp[32];
    float4 r0 = rp[0], r1 = rp[32];
    float4 x0 = make_float4(y0.x + r0.x, y0.y + r0.y, y0.z + r0.z, y0.w + r0.w);
    float4 x1 = make_float4(y1.x + r1.x, y1.y + r1.y, y1.z + r1.z, y1.w + r1.w);

    float s  = x0.x + x0.y + x0.z + x0.w + x1.x + x1.y + x1.z + x1.w;
    float sq = x0.x * x0.x + x0.y * x0.y + x0.z * x0.z + x0.w * x0.w
             + x1.x * x1.x + x1.y * x1.y + x1.z * x1.z + x1.w * x1.w;
#pragma unroll
    for (int off = 16; off >= 1; off >>= 1) {
        s  += __shfl_xor_sync(0xffffffffu, s,  off);
        sq += __shfl_xor_sync(0xffffffffu, sq, off);
    }
    if (lane == 0) psum[warp] = make_float2(s, sq);
    __syncthreads();
    {
        float2 a = psum[rloc * 4 + 0], b = psum[rloc * 4 + 1];
        float2 c = psum[rloc * 4 + 2], d = psum[rloc * 4 + 3];
        s  = a.x + b.x + c.x + d.x;
        sq = a.y + b.y + c.y + d.y;
    }
    const float mean = s * (1.f / 1024.f);
    const float inv  = rsqrtf(sq * (1.f / 1024.f) - mean * mean + 1e-6f);

    const float4* gp = (const float4*)gamma + f4;
    const float4* bp = (const float4*)beta  + f4;
    float4 g0 = gp[0], g1 = gp[32];
    float4 b0 = bp[0], b1 = bp[32];
    float4* op = (float4*)(out + (size_t)row * 1024) + f4;
    __stcs(op, make_float4((x0.x - mean) * inv * g0.x + b0.x,
                           (x0.y - mean) * inv * g0.y + b0.y,
                           (x0.z - mean) * inv * g0.z + b0.z,
                           (x0.w - mean) * inv * g0.w + b0.w));
    __stcs(op + 32, make_float4((x1.x - mean) * inv * g1.x + b1.x,
                                (x1.y - mean) * inv * g1.y + b1.y,
                                (x1.z - mean) * inv * g1.z + b1.z,
                                (x1.w - mean) * inv * g1.w + b1.w));
}

// ---------------------------------------------------------------------------
extern "C" void kernel_launch(void* const* d_in, const int* in_sizes, int n_in,
                              void* d_out, int out_size) {
    (void)in_sizes; (void)n_in; (void)out_size;
    const float* q     = (const float*)d_in[0];
    const float* v     = (const float*)d_in[2];
    const float* Wv    = (const float*)d_in[6];
    const float* Wo    = (const float*)d_in[7];
    const float* gamma = (const float*)d_in[8];
    const float* beta  = (const float*)d_in[9];
    float* out = (float*)d_out;

    float *part, *rowpart, *wosum, *outrows;
    cudaGetSymbolAddress((void**)&part,    g_part);
    cudaGetSymbolAddress((void**)&rowpart, g_rowpart);
    cudaGetSymbolAddress((void**)&wosum,   g_wosum);
    cudaGetSymbolAddress((void**)&outrows, g_outrows);

    pm_kernel<<<672, 256>>>(v, Wo, Wv, part, wosum, rowpart, outrows);
    ln_kernel<<<2048, 256>>>(outrows, q, gamma, beta, out);
}

// round 14
// speedup vs baseline: 1.1662x; 1.1662x over previous
#include <cuda_runtime.h>

// Scratch (device globals — no runtime allocation allowed)
__device__ float g_part   [4 * 64 * 1024];  // partial column sums of v (64 chunks of 16 rows)
__device__ float g_rowpart[8 * 4 * 1024];   // split-K partials of vsum @ Wv
__device__ float g_wosum  [64 * 1024];      // WoSum[d][m] = sum_j Wo[j*64+d][m]
__device__ float g_outrows[64 * 1024];      // 16 distinct out rows per batch
__device__ unsigned int g_fc, g_fw, g_f2;   // phase counters (reset by ln node)

static __device__ __forceinline__ void f4add(float4& a, const float4& b) {
    a.x += b.x; a.y += b.y; a.z += b.z; a.w += b.w;
}

static __device__ __forceinline__ void signal(unsigned int* f) {
    __threadfence();
    __syncthreads();
    if (threadIdx.x == 0) atomicAdd(f, 1u);
}

static __device__ __forceinline__ void spin_until(unsigned int* f, unsigned int tgt) {
    if (threadIdx.x == 0) {
        while (atomicAdd(f, 0u) < tgt) { }
    }
    __syncthreads();
    __threadfence();
}

// ---------------------------------------------------------------------------
// Node 1 (416 blocks, all wave-1 resident; 34KB smem -> 6 blocks/SM -> 888 cap):
//   [0,256)   colsum of v (16-row chunks)          -> g_fc (256)
//   [256,320) wosum of Wo                          -> g_fw (64)
//   [320,352) vwv producers  (wait fc)             -> g_f2 (32)
//   [352,416) outrows        (wait fw, then f2)
// (exact R12 configuration — proven 23.04 us)
// ---------------------------------------------------------------------------
__global__ __launch_bounds__(256) void pm_kernel(const float* __restrict__ v,
                                                 const float* __restrict__ Wo,
                                                 const float* __restrict__ Wv,
                                                 float* __restrict__ part,
                                                 float* __restrict__ wosum,
                                                 float* __restrict__ rowpart,
                                                 float* __restrict__ outrows) {
    __shared__ float smem_buf[64 * 128 + 8 * 64];   // 34 KB union
    const int bx = blockIdx.x;
    const int t  = threadIdx.x;

    if (bx < 256) {
        // ---- colsum of v: 16-row chunk ----
        const int s = bx >> 2, b = bx & 3;
        const float4* p = (const float4*)(v + ((size_t)(b * 1024 + s * 16)) * 1024) + t;
        float4 a0 = make_float4(0.f, 0.f, 0.f, 0.f);
        float4 a1 = make_float4(0.f, 0.f, 0.f, 0.f);
#pragma unroll
        for (int i = 0; i < 16; i += 2) {
            float4 x = p[(size_t)i * 256];
            float4 y = p[(size_t)(i + 1) * 256];
            f4add(a0, x);
            f4add(a1, y);
        }
        f4add(a0, a1);
        ((float4*)(part + (size_t)(b * 64 + s) * 1024))[t] = a0;
        signal(&g_fc);
    } else if (bx < 320) {
        // ---- wosum ----
        const int d = bx - 256;      // 0..63
        const float4* src = (const float4*)(Wo + (size_t)d * 1024) + t;
        float4 a0 = make_float4(0.f, 0.f, 0.f, 0.f);
        float4 a1 = make_float4(0.f, 0.f, 0.f, 0.f);
        float4 a2 = make_float4(0.f, 0.f, 0.f, 0.f);
        float4 a3 = make_float4(0.f, 0.f, 0.f, 0.f);
#pragma unroll
        for (int j = 0; j < 16; j += 4) {
            float4 x0 = src[(size_t)(j + 0) * 64 * 256];
            float4 x1 = src[(size_t)(j + 1) * 64 * 256];
            float4 x2 = src[(size_t)(j + 2) * 64 * 256];
            float4 x3 = src[(size_t)(j + 3) * 64 * 256];
            f4add(a0, x0); f4add(a1, x1); f4add(a2, x2); f4add(a3, x3);
        }
        f4add(a0, a1); f4add(a2, a3); f4add(a0, a2);
        ((float4*)(wosum + (size_t)d * 1024))[t] = a0;
        signal(&g_fw);
    } else if (bx < 352) {
        // ---- vwv producer: fold part, partial GEMM vs Wv ----
        float* vs = smem_buf;                        // [4][128]
        const int r = bx - 320, oc = r & 3, kc = r >> 2;
        spin_until(&g_fc, 256u);
        for (int idx = t; idx < 512; idx += 256) {
            int b = idx >> 7, kk = idx & 127;
            const float* pp = part + (size_t)(b * 64) * 1024 + kc * 128 + kk;
            float acc = 0.f;
            float buf[8];
#pragma unroll
            for (int g = 0; g < 8; ++g) {
#pragma unroll
                for (int i = 0; i < 8; ++i) buf[i] = pp[(size_t)(g * 8 + i) * 1024];
#pragma unroll
                for (int i = 0; i < 8; ++i) acc += buf[i];
            }
            vs[b * 128 + kk] = acc;
        }
        __syncthreads();
        const int o = oc * 256 + t;
        float a0 = 0.f, a1 = 0.f, a2 = 0.f, a3 = 0.f;
#pragma unroll 8
        for (int kk = 0; kk < 128; ++kk) {
            float w = Wv[(size_t)(kc * 128 + kk) * 1024 + o];
            a0 = fmaf(vs[0 * 128 + kk], w, a0);
            a1 = fmaf(vs[1 * 128 + kk], w, a1);
            a2 = fmaf(vs[2 * 128 + kk], w, a2);
            a3 = fmaf(vs[3 * 128 + kk], w, a3);
        }
        float* rp = rowpart + (size_t)kc * 4096;
        rp[0 * 1024 + o] = a0;
        rp[1 * 1024 + o] = a1;
        rp[2 * 1024 + o] = a2;
        rp[3 * 1024 + o] = a3;
        signal(&g_f2);
    } else {
        // ---- outrows consumer ----
        float4* ws = (float4*)smem_buf;              // [64][32] float4
        float*  rs = smem_buf + 64 * 128;            // [8][64]
        const int r = bx - 352;
        const int mc = r & 7, bng = r >> 3;

        // stage wosum tile once the wosum blocks are done
        spin_until(&g_fw, 64u);
#pragma unroll
        for (int it = 0; it < 8; ++it) {
            int idx = t + it * 256;            // 0..2047
            int d = idx >> 5, m4 = idx & 31;
            ws[d * 32 + m4] = *((const float4*)(wosum + (size_t)d * 1024 + mc * 128) + m4);
        }

        // wait for all vwv producers
        spin_until(&g_f2, 32u);
#pragma unroll
        for (int it = 0; it < 2; ++it) {
            int idx = t + it * 256;            // 0..511
            int bnl = idx >> 6, d = idx & 63;
            int bn = bng * 8 + bnl;
            int b = bn >> 4, o = (bn & 15) * 64 + d;
            float buf[8];
#pragma unroll
            for (int kc = 0; kc < 8; ++kc)
                buf[kc] = rowpart[(size_t)(kc * 4 + b) * 1024 + o];
            float a = 0.f;
#pragma unroll
            for (int kc = 0; kc < 8; ++kc) a += buf[kc];
            rs[bnl * 64 + d] = a;
        }
        __syncthreads();

        const int bnl = t >> 5, m4 = t & 31;   // warp = bnl -> rs broadcast
        float4 acc = make_float4(0.f, 0.f, 0.f, 0.f);
#pragma unroll
        for (int d = 0; d < 64; ++d) {
            float a = rs[bnl * 64 + d];
            float4 w = ws[d * 32 + m4];
            acc.x = fmaf(a, w.x, acc.x);
            acc.y = fmaf(a, w.y, acc.y);
            acc.z = fmaf(a, w.z, acc.z);
            acc.w = fmaf(a, w.w, acc.w);
        }
        const int bn = bng * 8 + bnl;
        *((float4*)(outrows + (size_t)bn * 1024 + mc * 128) + m4) = acc;
    }
}

// ---------------------------------------------------------------------------
// Node 2: residual add + LayerNorm, EIGHT WARPS PER ROW (1 row/block).
// Thread owns exactly 1 float4 of q + 1 of outrows. Grid 4096.
// Block 0 thread 0 resets the phase counters for the next graph replay.
// ---------------------------------------------------------------------------
__global__ __launch_bounds__(256) void ln_kernel(const float* __restrict__ outrows,
                                                 const float* __restrict__ q,
                                                 const float* __restrict__ gamma,
                                                 const float* __restrict__ beta,
                                                 float* __restrict__ out) {
    __shared__ float2 psum[8];
    if (blockIdx.x == 0 && threadIdx.x == 0) {
        g_fc = 0u; g_fw = 0u; g_f2 = 0u;   // safe: pm node fully done
    }
    const int t    = threadIdx.x;
    const int warp = t >> 5, lane = t & 31;
    const int row  = blockIdx.x;                       // 0..4095
    const int bn   = (row >> 10) * 16 + ((row & 1023) >> 6);

    const float4 y = ((const float4*)(outrows + (size_t)bn * 1024))[t];
    const float4 r = ((const float4*)(q + (size_t)row * 1024))[t];
    float4 x = make_float4(y.x + r.x, y.y + r.y, y.z + r.z, y.w + r.w);

    float s  = x.x + x.y + x.z + x.w;
    float sq = x.x * x.x + x.y * x.y + x.z * x.z + x.w * x.w;
#pragma unroll
    for (int off = 16; off >= 1; off >>= 1) {
        s  += __shfl_xor_sync(0xffffffffu, s,  off);
        sq += __shfl_xor_sync(0xffffffffu, sq, off);
    }
    if (lane == 0) psum[warp] = make_float2(s, sq);
    __syncthreads();
    {
        float2 a0 = psum[0], a1 = psum[1], a2 = psum[2], a3 = psum[3];
        float2 a4 = psum[4], a5 = psum[5], a6 = psum[6], a7 = psum[7];
        s  = ((a0.x + a1.x) + (a2.x + a3.x)) + ((a4.x + a5.x) + (a6.x + a7.x));
        sq = ((a0.y + a1.y) + (a2.y + a3.y)) + ((a4.y + a5.y) + (a6.y + a7.y));
    }
    const float mean = s * (1.f / 1024.f);
    const float inv  = rsqrtf(sq * (1.f / 1024.f) - mean * mean + 1e-6f);

    const float4 g  = ((const float4*)gamma)[t];
    const float4 bt = ((const float4*)beta)[t];
    ((float4*)(out + (size_t)row * 1024))[t] =
        make_float4((x.x - mean) * inv * g.x + bt.x,
                    (x.y - mean) * inv * g.y + bt.y,
                    (x.z - mean) * inv * g.z + bt.z,
                    (x.w - mean) * inv * g.w + bt.w);
}

// ---------------------------------------------------------------------------
extern "C" void kernel_launch(void* const* d_in, const int* in_sizes, int n_in,
                              void* d_out, int out_size) {
    (void)in_sizes; (void)n_in; (void)out_size;
    const float* q     = (const float*)d_in[0];
    const float* v     = (const float*)d_in[2];
    const float* Wv    = (const float*)d_in[6];
    const float* Wo    = (const float*)d_in[7];
    const float* gamma = (const float*)d_in[8];
    const float* beta  = (const float*)d_in[9];
    float* out = (float*)d_out;

    float *part, *rowpart, *wosum, *outrows;
    cudaGetSymbolAddress((void**)&part,    g_part);
    cudaGetSymbolAddress((void**)&rowpart, g_rowpart);
    cudaGetSymbolAddress((void**)&wosum,   g_wosum);
    cudaGetSymbolAddress((void**)&outrows, g_outrows);

    pm_kernel<<<416, 256>>>(v, Wo, Wv, part, wosum, rowpart, outrows);
    ln_kernel<<<4096, 256>>>(outrows, q, gamma, beta, out);
}

// round 15
// speedup vs baseline: 1.3924x; 1.1939x over previous
#include <cuda_runtime.h>

// Scratch (device globals — no runtime allocation allowed)
__device__ float g_part   [4 * 64 * 1024];  // partial column sums of v (64 chunks of 16 rows)
__device__ float g_rowpart[32 * 4 * 1024];  // 32-way split-K partials of vsum @ Wv
__device__ float g_wosum  [64 * 1024];      // WoSum[d][m] = sum_j Wo[j*64+d][m]
__device__ float g_outrows[64 * 1024];      // 16 distinct out rows per batch
__device__ unsigned int g_fc, g_fw, g_f2;   // phase counters (reset by ln node)

static __device__ __forceinline__ void f4add(float4& a, const float4& b) {
    a.x += b.x; a.y += b.y; a.z += b.z; a.w += b.w;
}

static __device__ __forceinline__ void signal(unsigned int* f) {
    __threadfence();
    __syncthreads();
    if (threadIdx.x == 0) atomicAdd(f, 1u);
}

static __device__ __forceinline__ void spin_until(unsigned int* f, unsigned int tgt) {
    if (threadIdx.x == 0) {
        while (atomicAdd(f, 0u) < tgt) { }
    }
    __syncthreads();
    __threadfence();
}

// ---------------------------------------------------------------------------
// Node 1 (512 blocks, 34KB smem -> 6 blocks/SM -> 888 cap, all wave-1 resident):
//   [0,256)   colsum of v (16-row chunks)                    -> g_fc (256)
//   [256,320) wosum of Wo                                    -> g_fw (64)
//   [320,448) vwv: stage 32KB Wv chunk to smem BEFORE the fc
//             spin (overlaps colsum!), then fold+FMA          -> g_f2 (128)
//   [448,512) outrows (wait fw -> ws tile; wait f2 -> rs; GEMM)
// ---------------------------------------------------------------------------
__global__ __launch_bounds__(256) void pm_kernel(const float* __restrict__ v,
                                                 const float* __restrict__ Wo,
                                                 const float* __restrict__ Wv,
                                                 float* __restrict__ part,
                                                 float* __restrict__ wosum,
                                                 float* __restrict__ rowpart,
                                                 float* __restrict__ outrows) {
    __shared__ float smem_buf[64 * 128 + 8 * 64];   // 34 KB union
    const int bx = blockIdx.x;
    const int t  = threadIdx.x;

    if (bx < 256) {
        // ---- colsum of v: 16-row chunk ----
        const int s = bx >> 2, b = bx & 3;
        const float4* p = (const float4*)(v + ((size_t)(b * 1024 + s * 16)) * 1024) + t;
        float4 a0 = make_float4(0.f, 0.f, 0.f, 0.f);
        float4 a1 = make_float4(0.f, 0.f, 0.f, 0.f);
#pragma unroll
        for (int i = 0; i < 16; i += 2) {
            float4 x = p[(size_t)i * 256];
            float4 y = p[(size_t)(i + 1) * 256];
            f4add(a0, x);
            f4add(a1, y);
        }
        f4add(a0, a1);
        ((float4*)(part + (size_t)(b * 64 + s) * 1024))[t] = a0;
        signal(&g_fc);
    } else if (bx < 320) {
        // ---- wosum ----
        const int d = bx - 256;      // 0..63
        const float4* src = (const float4*)(Wo + (size_t)d * 1024) + t;
        float4 a0 = make_float4(0.f, 0.f, 0.f, 0.f);
        float4 a1 = make_float4(0.f, 0.f, 0.f, 0.f);
        float4 a2 = make_float4(0.f, 0.f, 0.f, 0.f);
        float4 a3 = make_float4(0.f, 0.f, 0.f, 0.f);
#pragma unroll
        for (int j = 0; j < 16; j += 4) {
            float4 x0 = src[(size_t)(j + 0) * 64 * 256];
            float4 x1 = src[(size_t)(j + 1) * 64 * 256];
            float4 x2 = src[(size_t)(j + 2) * 64 * 256];
            float4 x3 = src[(size_t)(j + 3) * 64 * 256];
            f4add(a0, x0); f4add(a1, x1); f4add(a2, x2); f4add(a3, x3);
        }
        f4add(a0, a1); f4add(a2, a3); f4add(a0, a2);
        ((float4*)(wosum + (size_t)d * 1024))[t] = a0;
        signal(&g_fw);
    } else if (bx < 448) {
        // ---- vwv: 128 blocks; kc = 32 k's, oc = 256 o's ----
        float* wvs = smem_buf;             // [32 kk][256 o] = 32 KB
        float* vs  = smem_buf + 8192;      // [4 b][32 kk]
        const int r = bx - 320, oc = r & 3, kc = r >> 2;  // kc 0..31
        const int k0 = kc * 32, o0 = oc * 256;

        // Stage the Wv chunk NOW — independent of colsum, overlaps it.
        {
            const float4* wv4 = (const float4*)Wv;
#pragma unroll
            for (int it = 0; it < 8; ++it) {
                int idx = t + it * 256;            // 0..2047
                int kk = idx >> 6, o4 = idx & 63;
                ((float4*)wvs)[kk * 64 + o4] = wv4[(size_t)(k0 + kk) * 256 + oc * 64 + o4];
            }
        }

        spin_until(&g_fc, 256u);

        // Fold part -> vs for our 32 k's (128 values; threads 0..127)
        if (t < 128) {
            const int b = t >> 5, kk = t & 31;
            const float* pp = part + (size_t)(b * 64) * 1024 + k0 + kk;
            float acc = 0.f;
            float buf[8];
#pragma unroll
            for (int g = 0; g < 8; ++g) {
#pragma unroll
                for (int i = 0; i < 8; ++i) buf[i] = pp[(size_t)(g * 8 + i) * 1024];
#pragma unroll
                for (int i = 0; i < 8; ++i) acc += buf[i];
            }
            vs[b * 32 + kk] = acc;
        }
        __syncthreads();

        const int o = o0 + t;
        float a0 = 0.f, a1 = 0.f, a2 = 0.f, a3 = 0.f;
#pragma unroll
        for (int kk = 0; kk < 32; ++kk) {
            float w = wvs[kk * 256 + t];
            a0 = fmaf(vs[0 * 32 + kk], w, a0);
            a1 = fmaf(vs[1 * 32 + kk], w, a1);
            a2 = fmaf(vs[2 * 32 + kk], w, a2);
            a3 = fmaf(vs[3 * 32 + kk], w, a3);
        }
        float* rp = rowpart + (size_t)kc * 4096;
        rp[0 * 1024 + o] = a0;
        rp[1 * 1024 + o] = a1;
        rp[2 * 1024 + o] = a2;
        rp[3 * 1024 + o] = a3;
        signal(&g_f2);
    } else {
        // ---- outrows consumer ----
        float4* ws = (float4*)smem_buf;              // [64][32] float4
        float*  rs = smem_buf + 64 * 128;            // [8][64]
        const int r = bx - 448;
        const int mc = r & 7, bng = r >> 3;

        // stage wosum tile once the wosum blocks are done
        spin_until(&g_fw, 64u);
#pragma unroll
        for (int it = 0; it < 8; ++it) {
            int idx = t + it * 256;            // 0..2047
            int d = idx >> 5, m4 = idx & 31;
            ws[d * 32 + m4] = *((const float4*)(wosum + (size_t)d * 1024 + mc * 128) + m4);
        }

        // wait for all vwv producers, fold 32-way split-K
        spin_until(&g_f2, 128u);
#pragma unroll
        for (int it = 0; it < 2; ++it) {
            int idx = t + it * 256;            // 0..511
            int bnl = idx >> 6, d = idx & 63;
            int bn = bng * 8 + bnl;
            int b = bn >> 4, o = (bn & 15) * 64 + d;
            const float* rp = rowpart + (size_t)b * 1024 + o;
            float acc = 0.f;
            float buf[8];
#pragma unroll
            for (int g = 0; g < 4; ++g) {
#pragma unroll
                for (int i = 0; i < 8; ++i) buf[i] = rp[(size_t)((g * 8 + i) * 4) * 1024];
#pragma unroll
                for (int i = 0; i < 8; ++i) acc += buf[i];
            }
            rs[bnl * 64 + d] = acc;
        }
        __syncthreads();

        const int bnl = t >> 5, m4 = t & 31;   // warp = bnl -> rs broadcast
        float4 acc = make_float4(0.f, 0.f, 0.f, 0.f);
#pragma unroll
        for (int d = 0; d < 64; ++d) {
            float a = rs[bnl * 64 + d];
            float4 w = ws[d * 32 + m4];
            acc.x = fmaf(a, w.x, acc.x);
            acc.y = fmaf(a, w.y, acc.y);
            acc.z = fmaf(a, w.z, acc.z);
            acc.w = fmaf(a, w.w, acc.w);
        }
        const int bn = bng * 8 + bnl;
        *((float4*)(outrows + (size_t)bn * 1024 + mc * 128) + m4) = acc;
    }
}

// ---------------------------------------------------------------------------
// Node 2: residual add + LayerNorm, FOUR WARPS PER ROW (R12's best version).
// Block 0 thread 0 resets the phase counters for the next graph replay.
// ---------------------------------------------------------------------------
__global__ __launch_bounds__(256) void ln_kernel(const float* __restrict__ outrows,
                                                 const float* __restrict__ q,
                                                 const float* __restrict__ gamma,
                                                 const float* __restrict__ beta,
                                                 float* __restrict__ out) {
    __shared__ float2 psum[8];
    if (blockIdx.x == 0 && threadIdx.x == 0) {
        g_fc = 0u; g_fw = 0u; g_f2 = 0u;   // safe: pm node fully done
    }
    const int warp = threadIdx.x >> 5, lane = threadIdx.x & 31;
    const int rloc = warp >> 2, qtr = warp & 3;
    const int row  = blockIdx.x * 2 + rloc;            // 0..4095
    const int bn   = (row >> 10) * 16 + ((row & 1023) >> 6);
    const int f4   = qtr * 64 + lane;                  // float4 index base

    const float4* yp = (const float4*)(outrows + (size_t)bn * 1024) + f4;
    const float4* rp = (const float4*)(q + (size_t)row * 1024) + f4;

    float4 y0 = yp[0], y1 = yp[32];
    float4 r0 = rp[0], r1 = rp[32];
    float4 x0 = make_float4(y0.x + r0.x, y0.y + r0.y, y0.z + r0.z, y0.w + r0.w);
    float4 x1 = make_float4(y1.x + r1.x, y1.y + r1.y, y1.z + r1.z, y1.w + r1.w);

    float s  = x0.x + x0.y + x0.z + x0.w + x1.x + x1.y + x1.z + x1.w;
    float sq = x0.x * x0.x + x0.y * x0.y + x0.z * x0.z + x0.w * x0.w
             + x1.x * x1.x + x1.y * x1.y + x1.z * x1.z + x1.w * x1.w;
#pragma unroll
    for (int off = 16; off >= 1; off >>= 1) {
        s  += __shfl_xor_sync(0xffffffffu, s,  off);
        sq += __shfl_xor_sync(0xffffffffu, sq, off);
    }
    if (lane == 0) psum[warp] = make_float2(s, sq);
    __syncthreads();
    {
        float2 a = psum[rloc * 4 + 0], b = psum[rloc * 4 + 1];
        float2 c = psum[rloc * 4 + 2], d = psum[rloc * 4 + 3];
        s  = a.x + b.x + c.x + d.x;
        sq = a.y + b.y + c.y + d.y;
    }
    const float mean = s * (1.f / 1024.f);
    const float inv  = rsqrtf(sq * (1.f / 1024.f) - mean * mean + 1e-6f);

    const float4* gp = (const float4*)gamma + f4;
    const float4* bp = (const float4*)beta  + f4;
    float4 g0 = gp[0], g1 = gp[32];
    float4 b0 = bp[0], b1 = bp[32];
    float4* op = (float4*)(out + (size_t)row * 1024) + f4;
    op[0]  = make_float4((x0.x - mean) * inv * g0.x + b0.x,
                         (x0.y - mean) * inv * g0.y + b0.y,
                         (x0.z - mean) * inv * g0.z + b0.z,
                         (x0.w - mean) * inv * g0.w + b0.w);
    op[32] = make_float4((x1.x - mean) * inv * g1.x + b1.x,
                         (x1.y - mean) * inv * g1.y + b1.y,
                         (x1.z - mean) * inv * g1.z + b1.z,
                         (x1.w - mean) * inv * g1.w + b1.w);
}

// ---------------------------------------------------------------------------
extern "C" void kernel_launch(void* const* d_in, const int* in_sizes, int n_in,
                              void* d_out, int out_size) {
    (void)in_sizes; (void)n_in; (void)out_size;
    const float* q     = (const float*)d_in[0];
    const float* v     = (const float*)d_in[2];
    const float* Wv    = (const float*)d_in[6];
    const float* Wo    = (const float*)d_in[7];
    const float* gamma = (const float*)d_in[8];
    const float* beta  = (const float*)d_in[9];
    float* out = (float*)d_out;

    float *part, *rowpart, *wosum, *outrows;
    cudaGetSymbolAddress((void**)&part,    g_part);
    cudaGetSymbolAddress((void**)&rowpart, g_rowpart);
    cudaGetSymbolAddress((void**)&wosum,   g_wosum);
    cudaGetSymbolAddress((void**)&outrows, g_outrows);

    pm_kernel<<<512, 256>>>(v, Wo, Wv, part, wosum, rowpart, outrows);
    ln_kernel<<<2048, 256>>>(outrows, q, gamma, beta, out);
}